// round 13
// baseline (speedup 1.0000x reference)
#include <cuda_runtime.h>
#include <cuda_bf16.h>
#include <math.h>
#include <stdint.h>

#define DDIM 256
#define MAXN 131072
#define MAXK 1024
#define NPART 16384   // MAXN / 8 rows-per-output-block

// ---------------- device scratch (no allocations allowed) ----------------
__device__ uint2  g_X8[MAXN * DDIM / 8];   // int8 X (scale 32)
__device__ uint2  g_C8[MAXK * DDIM / 8];   // int8 C (scale 32)
__device__ float  g_cnorm[MAXK];
__device__ int    g_cand[MAXN * 8];        // 6 candidates + 2 pad per row
__device__ int    g_hist[MAXK];
__device__ double g_ssep[NPART];

// ---------------- PTX helpers (plain sm_80-class PTX only) ----------------
__device__ __forceinline__ uint32_t smem_u32(const void* p) {
    uint32_t a;
    asm("{ .reg .u64 t; cvta.to.shared.u64 t, %1; cvt.u32.u64 %0, t; }" : "=r"(a) : "l"(p));
    return a;
}
#define CP_ASYNC16(dst, src) \
    asm volatile("cp.async.cg.shared.global [%0], [%1], 16;" :: "r"(dst), "l"(src))
#define CP_COMMIT()  asm volatile("cp.async.commit_group;" ::: "memory")
#define CP_WAIT(n)   asm volatile("cp.async.wait_group %0;" :: "n"(n) : "memory")

__device__ __forceinline__ void ldm_x4(uint32_t* r, uint32_t addr) {
    asm volatile("ldmatrix.sync.aligned.m8n8.x4.shared.b16 {%0,%1,%2,%3}, [%4];"
                 : "=r"(r[0]), "=r"(r[1]), "=r"(r[2]), "=r"(r[3]) : "r"(addr));
}
// int8 IMMA, s32 accumulate. k32 byte-fragments = bf16 k16 fragments (b16 = 2 bytes).
__device__ __forceinline__ void imma16832(int* c, const uint32_t* a, const uint32_t* b) {
    asm volatile(
        "mma.sync.aligned.m16n8k32.row.col.s32.s8.s8.s32 "
        "{%0,%1,%2,%3}, {%4,%5,%6,%7}, {%8,%9}, {%0,%1,%2,%3};"
        : "+r"(c[0]), "+r"(c[1]), "+r"(c[2]), "+r"(c[3])
        : "r"(a[0]), "r"(a[1]), "r"(a[2]), "r"(a[3]), "r"(b[0]), "r"(b[1]));
}
__device__ __forceinline__ int q8(float v) {
    return __float2int_rn(fminf(fmaxf(v * 32.f, -127.f), 127.f));
}

// ---------------------------------------------------------------------------
__global__ void vq_zero_kernel(int K)
{
    int t = blockIdx.x * blockDim.x + threadIdx.x;
    if (t < K) g_hist[t] = 0;
}

// ---------------------------------------------------------------------------
__global__ void vq_cnorm_kernel(const float* __restrict__ C, int K)
{
    int warp = (blockIdx.x * blockDim.x + threadIdx.x) >> 5;
    int lane = threadIdx.x & 31;
    if (warp >= K) return;
    const float4* cp = (const float4*)(C + (size_t)warp * DDIM);
    float s = 0.f;
#pragma unroll
    for (int i = 0; i < 2; i++) {
        float4 v = cp[lane + i * 32];
        s += v.x * v.x + v.y * v.y + v.z * v.z + v.w * v.w;
    }
#pragma unroll
    for (int o = 16; o > 0; o >>= 1) s += __shfl_down_sync(0xffffffffu, s, o);
    if (lane == 0) g_cnorm[warp] = s;
}

// ---------------------------------------------------------------------------
// fp32 -> int8 (scale 32, rn, clamp +-127); 8 elems / thread.
// IMPORTANT: destination globals selected in DEVICE code (mode flag) —
// passing __device__ array addresses from host is invalid (R8/R9/R11 bug).
// ---------------------------------------------------------------------------
__global__ void vq_convert8_kernel(const float* __restrict__ src, int mode,
                                   int off8, int n8)
{
    int t = blockIdx.x * blockDim.x + threadIdx.x;
    if (t >= n8) return;
    const float4* s4 = (const float4*)src;
    float4 a = s4[t * 2], b = s4[t * 2 + 1];
    uint2 r;
    r.x = (uint32_t)(q8(a.x) & 255) | ((uint32_t)(q8(a.y) & 255) << 8)
        | ((uint32_t)(q8(a.z) & 255) << 16) | ((uint32_t)(q8(a.w) & 255) << 24);
    r.y = (uint32_t)(q8(b.x) & 255) | ((uint32_t)(q8(b.y) & 255) << 8)
        | ((uint32_t)(q8(b.z) & 255) << 16) | ((uint32_t)(q8(b.w) & 255) << 24);
    uint2* dst = (mode ? g_C8 : g_X8) + off8;
    dst[t] = r;
}

// ---------------------------------------------------------------------------
// int8 IMMA distance GEMM + per-row top-6 candidates.
// score(n,k) ~= ||c_k||^2 - 2 * (x8.c8)/1024   (s32 dot exact; quantization
// score sigma ~0.4 vs order-stat gaps ~16 -> exact argmin in top-6 w.p. ~1;
// exact fp32 re-rank downstream).
// CTA: 128 rows resident (A 32 KB), 8 passes of 128 codes; full K=256 B-tile
// (32 KB) per pass, double-buffered. Warps 4(M)x2(N), warp tile 32x64,
// 8 k-steps of k32 per pass. (Structure = R9 GEMM, which executed cleanly.)
// ---------------------------------------------------------------------------
#define SM_CN 0            // 4 KB cnorm
#define SM_A  4096         // 32 KB: A int8 (row 256B, swizzled)
#define SM_B  36864        // 2 stages x 32 KB
#define SMEM_BYTES 102400

__global__ __launch_bounds__(256, 2) void vq_gemm_kernel()
{
    extern __shared__ char smem[];
    const uint32_t sb = smem_u32(smem);
    const int tid  = threadIdx.x;
    const int lane = tid & 31;
    const int wid  = tid >> 5;
    const int wm0  = (wid >> 1) * 32;     // warp M origin (4)
    const int wn0  = (wid & 1) * 64;      // warp N origin (2)
    const int brow = blockIdx.x * 128;
    const uint8_t* Xb = (const uint8_t*)g_X8;   // device-side global refs (legal)
    const uint8_t* Cb = (const uint8_t*)g_C8;

    // ---- cnorm (4 KB) + resident A (32 KB) + B pass0 via cp.async ----
    CP_ASYNC16(sb + SM_CN + tid * 16, g_cnorm + tid * 4);
#pragma unroll
    for (int it = 0; it < 8; it++) {
        int li  = tid + it * 256;           // 0..2047
        int row = li >> 4, u = li & 15;
        uint32_t sw = (uint32_t)((u & 8) | ((u & 7) ^ (row & 7)));
        CP_ASYNC16(sb + SM_A + row * 256 + sw * 16,
                   Xb + (size_t)(brow + row) * DDIM + u * 16);
    }
#pragma unroll
    for (int it = 0; it < 8; it++) {        // B pass 0 -> stage 0
        int li = tid + it * 256;
        int code = li >> 4, u = li & 15;
        uint32_t sw = (uint32_t)((u & 8) | ((u & 7) ^ (code & 7)));
        CP_ASYNC16(sb + SM_B + code * 256 + sw * 16,
                   Cb + (size_t)code * DDIM + u * 16);
    }
    CP_COMMIT();

    // per-thread top-3 for 4 row-slots
    float tv[4][3];
    int   ti[4][3];
#pragma unroll
    for (int i = 0; i < 4; i++)
#pragma unroll
        for (int j = 0; j < 3; j++) { tv[i][j] = 3.4e38f; ti[i][j] = 0x7FFFFFFF; }

    const float* cn = (const float*)smem;

    for (int p = 0; p < 8; p++) {
        const int kt = p * 128;
        const int st = p & 1;
        if (p < 7) {   // prefetch next pass's B into other stage
#pragma unroll
            for (int it = 0; it < 8; it++) {
                int li = tid + it * 256;
                int code = li >> 4, u = li & 15;
                uint32_t sw = (uint32_t)((u & 8) | ((u & 7) ^ (code & 7)));
                CP_ASYNC16(sb + SM_B + (st ^ 1) * 32768 + code * 256 + sw * 16,
                           Cb + (size_t)(kt + 128 + code) * DDIM + u * 16);
            }
            CP_COMMIT();
            CP_WAIT(1);
        } else {
            CP_WAIT(0);
        }
        __syncthreads();

        int acc[2][8][4];
#pragma unroll
        for (int im = 0; im < 2; im++)
#pragma unroll
            for (int jn = 0; jn < 8; jn++)
#pragma unroll
                for (int e = 0; e < 4; e++) acc[im][jn][e] = 0;

#pragma unroll
        for (int ksl = 0; ksl < 8; ksl++) {   // k32 steps over K=256
            uint32_t ah[8], bh[16];
            const int uA = ksl * 2 + (lane >> 4);
#pragma unroll
            for (int im = 0; im < 2; im++) {
                int row = wm0 + im * 16 + (lane & 15);
                uint32_t sw = (uint32_t)((uA & 8) | ((uA & 7) ^ (row & 7)));
                ldm_x4(&ah[im * 4], sb + SM_A + row * 256 + sw * 16);
            }
            const int uB = ksl * 2 + ((lane >> 3) & 1);
#pragma unroll
            for (int j4 = 0; j4 < 4; j4++) {
                int code = wn0 + j4 * 16 + ((lane >> 4) * 8) + (lane & 7);
                uint32_t sw = (uint32_t)((uB & 8) | ((uB & 7) ^ (code & 7)));
                ldm_x4(&bh[j4 * 4], sb + SM_B + st * 32768 + code * 256 + sw * 16);
            }
#pragma unroll
            for (int im = 0; im < 2; im++)
#pragma unroll
                for (int jn = 0; jn < 8; jn++)
                    imma16832(acc[im][jn], &ah[im * 4],
                              &bh[(jn >> 1) * 4 + (jn & 1) * 2]);
        }

        // ---- epilogue: scores + per-thread running top-3 ----
        // dot_fp ~= acc / (32*32); score = cn - 2*dot = cn - acc/512
#pragma unroll
        for (int im = 0; im < 2; im++)
#pragma unroll
            for (int jn = 0; jn < 8; jn++)
#pragma unroll
                for (int e = 0; e < 4; e++) {
                    const int rs  = im * 2 + (e >> 1);
                    const int col = kt + wn0 + jn * 8 + (lane & 3) * 2 + (e & 1);
                    float s = fmaf(-1.953125e-3f, (float)acc[im][jn][e], cn[col]);
                    if (s < tv[rs][2]) {
                        if (s < tv[rs][1]) {
                            tv[rs][2] = tv[rs][1]; ti[rs][2] = ti[rs][1];
                            if (s < tv[rs][0]) {
                                tv[rs][1] = tv[rs][0]; ti[rs][1] = ti[rs][0];
                                tv[rs][0] = s;         ti[rs][0] = col;
                            } else { tv[rs][1] = s; ti[rs][1] = col; }
                        } else { tv[rs][2] = s; ti[rs][2] = col; }
                    }
                }
        __syncthreads();   // all warps done with stage st before refill
    }

    // ---- CTA merge: 8 contributors x 3 -> top-6 per row ----
    float* rv = (float*)(smem + SM_B);          // [128][8][3]
    int*   ri = (int*)(smem + SM_B + 12288);    // [128][8][3]
    const int cid = (wid & 1) * 4 + (lane & 3);
#pragma unroll
    for (int im = 0; im < 2; im++)
#pragma unroll
        for (int half = 0; half < 2; half++) {
            const int rs  = im * 2 + half;
            const int row = wm0 + im * 16 + (lane >> 2) + half * 8;
#pragma unroll
            for (int sl = 0; sl < 3; sl++) {
                rv[(row * 8 + cid) * 3 + sl] = tv[rs][sl];
                ri[(row * 8 + cid) * 3 + sl] = ti[rs][sl];
            }
        }
    __syncthreads();
    if (tid < 128) {
        float v[6]; int ix[6];
#pragma unroll
        for (int j = 0; j < 6; j++) { v[j] = 3.4e38f; ix[j] = 0x7FFFFFFF; }
        for (int c = 0; c < 24; c++) {
            float val = rv[tid * 24 + c];
            int   id  = ri[tid * 24 + c];
            if (val < v[5] || (val == v[5] && id < ix[5])) {
                v[5] = val; ix[5] = id;
#pragma unroll
                for (int j = 5; j > 0; j--) {
                    if (v[j] < v[j-1] || (v[j] == v[j-1] && ix[j] < ix[j-1])) {
                        float tv_ = v[j]; v[j] = v[j-1]; v[j-1] = tv_;
                        int   ti_ = ix[j]; ix[j] = ix[j-1]; ix[j-1] = ti_;
                    }
                }
            }
        }
        int* gc = g_cand + (size_t)(brow + tid) * 8;
        ((int4*)gc)[0] = make_int4(ix[0], ix[1], ix[2], ix[3]);
        ((int4*)gc)[1] = make_int4(ix[4], ix[5], ix[0], ix[0]);
    }
}

// ---------------------------------------------------------------------------
// Exact fp32 re-rank of 6 candidates + gather + straight-through output
// + SSE partials + histogram. One warp per row.
// ---------------------------------------------------------------------------
__global__ __launch_bounds__(256) void vq_output_kernel(
    const float* __restrict__ X, const float* __restrict__ C,
    float* __restrict__ outQ, float* __restrict__ outIdx, int N)
{
    __shared__ double wsse[8];
    int gw   = (blockIdx.x * 256 + threadIdx.x) >> 5;
    int lane = threadIdx.x & 31;
    int wib  = threadIdx.x >> 5;

    if (gw < N) {
        const int4 c0 = ((const int4*)(g_cand + (size_t)gw * 8))[0];
        const int4 c1 = ((const int4*)(g_cand + (size_t)gw * 8))[1];
        int cand[6] = { c0.x, c0.y, c0.z, c0.w, c1.x, c1.y };

        const float4* xp = (const float4*)(X + (size_t)gw * DDIM);
        float4 x0 = xp[lane], x1 = xp[lane + 32];

        float bestS = 3.4e38f;
        int   bestI = 0x7FFFFFFF;
        float4 bq0 = x0, bq1 = x1;
#pragma unroll
        for (int j = 0; j < 6; j++) {
            const int idx = cand[j];
            const float4* cp = (const float4*)(C + (size_t)idx * DDIM);
            float4 q0 = cp[lane], q1 = cp[lane + 32];
            float d = x0.x*q0.x + x0.y*q0.y + x0.z*q0.z + x0.w*q0.w
                    + x1.x*q1.x + x1.y*q1.y + x1.z*q1.z + x1.w*q1.w;
#pragma unroll
            for (int o = 16; o > 0; o >>= 1) d += __shfl_xor_sync(0xffffffffu, d, o);
            float s = g_cnorm[idx] - 2.f * d;
            bool better = (s < bestS) || (s == bestS && idx < bestI);
            if (better) { bestS = s; bestI = idx; bq0 = q0; bq1 = q1; }
        }

        float4 o0, o1;
        double sse = 0.0;
        float dx;
        dx = bq0.x - x0.x; o0.x = x0.x + dx; sse += (double)dx * dx;
        dx = bq0.y - x0.y; o0.y = x0.y + dx; sse += (double)dx * dx;
        dx = bq0.z - x0.z; o0.z = x0.z + dx; sse += (double)dx * dx;
        dx = bq0.w - x0.w; o0.w = x0.w + dx; sse += (double)dx * dx;
        dx = bq1.x - x1.x; o1.x = x1.x + dx; sse += (double)dx * dx;
        dx = bq1.y - x1.y; o1.y = x1.y + dx; sse += (double)dx * dx;
        dx = bq1.z - x1.z; o1.z = x1.z + dx; sse += (double)dx * dx;
        dx = bq1.w - x1.w; o1.w = x1.w + dx; sse += (double)dx * dx;

        float4* op = (float4*)(outQ + (size_t)gw * DDIM);
        op[lane] = o0;
        op[lane + 32] = o1;

#pragma unroll
        for (int o = 16; o > 0; o >>= 1) sse += __shfl_down_sync(0xffffffffu, sse, o);
        if (lane == 0) {
            wsse[wib] = sse;
            atomicAdd(&g_hist[bestI], 1);
            outIdx[gw] = (float)bestI;
        }
    } else if (lane == 0) {
        wsse[wib] = 0.0;
    }
    __syncthreads();
    if (threadIdx.x == 0) {
        double s = 0.0;
#pragma unroll
        for (int i = 0; i < 8; i++) s += wsse[i];
        g_ssep[blockIdx.x] = s;
    }
}

// ---------------------------------------------------------------------------
__global__ void vq_finalize_kernel(float* __restrict__ outS, int N, int K)
{
    __shared__ double red[256];
    int t = threadIdx.x;
    double s = 0.0;
    for (int i = t; i < NPART; i += 256) s += g_ssep[i];
    red[t] = s;
    __syncthreads();
    for (int st = 128; st > 0; st >>= 1) { if (t < st) red[t] += red[t + st]; __syncthreads(); }
    double sseTot = red[0];
    __syncthreads();

    double h = 0.0;
    for (int k = t; k < K; k += 256) {
        float pr = (float)g_hist[k] / (float)N;
        h += (double)(pr * logf(pr + 1e-10f));
    }
    red[t] = h;
    __syncthreads();
    for (int st = 128; st > 0; st >>= 1) { if (t < st) red[t] += red[t + st]; __syncthreads(); }
    if (t == 0) {
        double mean = sseTot / ((double)N * (double)DDIM);
        outS[0] = (float)(1.25 * mean);
        outS[1] = (float)exp(-red[0]);
    }
}

// ---------------------------------------------------------------------------
extern "C" void kernel_launch(void* const* d_in, const int* in_sizes, int n_in,
                              void* d_out, int out_size)
{
    const float* X = (const float*)d_in[0];   // [N, 256]
    const float* C = (const float*)d_in[1];   // [K, 256]
    const int N = in_sizes[0] / DDIM;         // 131072
    const int K = in_sizes[1] / DDIM;         // 1024

    float* out        = (float*)d_out;
    float* outQ       = out;                      // N*D quantized_st
    float* outIdx     = out + (size_t)N * DDIM;   // N indices (as f32)
    float* outScalars = outIdx + N;               // loss, perplexity

    static bool attr_set = false;
    if (!attr_set) {
        cudaFuncSetAttribute(vq_gemm_kernel,
                             cudaFuncAttributeMaxDynamicSharedMemorySize, SMEM_BYTES);
        attr_set = true;
    }

    const int n8C  = K * DDIM / 8;            // 32768
    const int n8Xh = N * DDIM / 16;           // half of X, 8-elem units

    vq_zero_kernel<<<(K + 255) / 256, 256>>>(K);                              // 1
    vq_cnorm_kernel<<<(K * 32 + 255) / 256, 256>>>(C, K);                     // 2
    vq_convert8_kernel<<<(n8C + 255) / 256, 256>>>(C, 1, 0, n8C);             // 3
    vq_convert8_kernel<<<(n8Xh + 255) / 256, 256>>>(X, 0, 0, n8Xh);           // 4
    vq_convert8_kernel<<<(n8Xh + 255) / 256, 256>>>(X + (size_t)n8Xh * 8, 0,
                                                    n8Xh, n8Xh);              // 5
    vq_gemm_kernel<<<N / 128, 256, SMEM_BYTES>>>();                           // 6 (ncu -s 5)
    vq_output_kernel<<<N / 8, 256>>>(X, C, outQ, outIdx, N);                  // 7
    vq_finalize_kernel<<<1, 256>>>(outScalars, N, K);                         // 8
}

// round 15
// speedup vs baseline: 1.5659x; 1.5659x over previous
#include <cuda_runtime.h>
#include <cuda_bf16.h>
#include <math.h>
#include <stdint.h>

#define DDIM 256
#define MAXN 131072
#define MAXK 1024
#define NPART 16384   // MAXN / 8 rows-per-output-block

// ---------------- device scratch (no allocations allowed) ----------------
__device__ __nv_bfloat16 g_Xb[MAXN * DDIM];
__device__ __nv_bfloat16 g_Cb[MAXK * DDIM];
__device__ float  g_cnorm[MAXK];
__device__ int    g_cand[MAXN * 8];     // 6 candidates + 2 pad per row
__device__ int    g_hist[MAXK];
__device__ double g_ssep[NPART];

// ---------------- PTX helpers (plain sm_80-class PTX only) ----------------
__device__ __forceinline__ uint32_t smem_u32(const void* p) {
    uint32_t a;
    asm("{ .reg .u64 t; cvta.to.shared.u64 t, %1; cvt.u32.u64 %0, t; }" : "=r"(a) : "l"(p));
    return a;
}
#define CP_ASYNC16(dst, src) \
    asm volatile("cp.async.cg.shared.global [%0], [%1], 16;" :: "r"(dst), "l"(src))
#define CP_COMMIT()  asm volatile("cp.async.commit_group;" ::: "memory")
#define CP_WAIT(n)   asm volatile("cp.async.wait_group %0;" :: "n"(n) : "memory")

__device__ __forceinline__ void ldm_x4(uint32_t* r, uint32_t addr) {
    asm volatile("ldmatrix.sync.aligned.m8n8.x4.shared.b16 {%0,%1,%2,%3}, [%4];"
                 : "=r"(r[0]), "=r"(r[1]), "=r"(r[2]), "=r"(r[3]) : "r"(addr));
}
__device__ __forceinline__ void mma16816(float* c, const uint32_t* a, const uint32_t* b) {
    asm volatile(
        "mma.sync.aligned.m16n8k16.row.col.f32.bf16.bf16.f32 "
        "{%0,%1,%2,%3}, {%4,%5,%6,%7}, {%8,%9}, {%0,%1,%2,%3};"
        : "+f"(c[0]), "+f"(c[1]), "+f"(c[2]), "+f"(c[3])
        : "r"(a[0]), "r"(a[1]), "r"(a[2]), "r"(a[3]), "r"(b[0]), "r"(b[1]));
}

// ---------------------------------------------------------------------------
__global__ void vq_zero_kernel(int K)
{
    int t = blockIdx.x * blockDim.x + threadIdx.x;
    if (t < K) g_hist[t] = 0;
}

// ---------------------------------------------------------------------------
__global__ void vq_cnorm_kernel(const float* __restrict__ C, int K)
{
    int warp = (blockIdx.x * blockDim.x + threadIdx.x) >> 5;
    int lane = threadIdx.x & 31;
    if (warp >= K) return;
    const float4* cp = (const float4*)(C + (size_t)warp * DDIM);
    float s = 0.f;
#pragma unroll
    for (int i = 0; i < 2; i++) {
        float4 v = cp[lane + i * 32];
        s += v.x * v.x + v.y * v.y + v.z * v.z + v.w * v.w;
    }
#pragma unroll
    for (int o = 16; o > 0; o >>= 1) s += __shfl_down_sync(0xffffffffu, s, o);
    if (lane == 0) g_cnorm[warp] = s;
}

// ---------------------------------------------------------------------------
// fp32 -> bf16 (rn), 8 elems / thread, 16B stores.
// Destination global selected in DEVICE code via mode flag (host-side
// __device__ symbol addresses are invalid — the R8/R9/R11 bug).
// ---------------------------------------------------------------------------
__global__ void vq_convert_kernel(const float* __restrict__ src, int mode, int n8)
{
    int t = blockIdx.x * blockDim.x + threadIdx.x;
    if (t >= n8) return;
    const float4* s4 = (const float4*)src;
    float4 a = s4[t * 2], b = s4[t * 2 + 1];
    uint4 r;
    r.x = (uint32_t)__bfloat16_as_ushort(__float2bfloat16(a.x))
        | ((uint32_t)__bfloat16_as_ushort(__float2bfloat16(a.y)) << 16);
    r.y = (uint32_t)__bfloat16_as_ushort(__float2bfloat16(a.z))
        | ((uint32_t)__bfloat16_as_ushort(__float2bfloat16(a.w)) << 16);
    r.z = (uint32_t)__bfloat16_as_ushort(__float2bfloat16(b.x))
        | ((uint32_t)__bfloat16_as_ushort(__float2bfloat16(b.y)) << 16);
    r.w = (uint32_t)__bfloat16_as_ushort(__float2bfloat16(b.z))
        | ((uint32_t)__bfloat16_as_ushort(__float2bfloat16(b.w)) << 16);
    uint4* dst = (uint4*)(mode ? g_Cb : g_Xb);
    dst[t] = r;
}

// ---------------------------------------------------------------------------
// bf16 HMMA distance GEMM + per-row top-6 candidates. EXACT R7 structure
// (proven green): per-pass B prologue, unrolled slab loop, two syncs/slab,
// top-3/thread -> top-6/CTA merge.
// ---------------------------------------------------------------------------
#define SM_CN 0            // 4 KB cnorm
#define SM_A  4096         // 64 KB: A bf16 (row 512B, swizzled)
#define SM_B  69632        // 2 stages x 16 KB
#define SMEM_BYTES 102400

__global__ __launch_bounds__(256, 2) void vq_gemm_kernel()
{
    extern __shared__ char smem[];
    const uint32_t sb = smem_u32(smem);
    const int tid  = threadIdx.x;
    const int lane = tid & 31;
    const int wid  = tid >> 5;
    const int wm0  = (wid >> 1) * 32;     // warp M origin (4)
    const int wn0  = (wid & 1) * 64;      // warp N origin (2)
    const int brow = blockIdx.x * 128;

    // ---- cnorm (4 KB) + resident A (64 KB) via cp.async ----
    CP_ASYNC16(sb + SM_CN + tid * 16, g_cnorm + tid * 4);
#pragma unroll
    for (int it = 0; it < 16; it++) {
        int li  = tid + it * 256;           // 0..4095
        int row = li >> 5, u = li & 31;
        uint32_t sw = (uint32_t)((u & 24) | ((u & 7) ^ (row & 7)));
        CP_ASYNC16(sb + SM_A + row * 512 + sw * 16,
                   g_Xb + (size_t)(brow + row) * DDIM + u * 8);
    }
    CP_COMMIT();

    // per-thread top-3 for 4 row-slots
    float tv[4][3];
    int   ti[4][3];
#pragma unroll
    for (int i = 0; i < 4; i++)
#pragma unroll
        for (int j = 0; j < 3; j++) { tv[i][j] = 3.4e38f; ti[i][j] = 0x7FFFFFFF; }

    CP_WAIT(0);
    __syncthreads();

    const float* cn = (const float*)smem;

    for (int p = 0; p < 8; p++) {
        const int kt = p * 128;

        float acc[2][8][4];
#pragma unroll
        for (int im = 0; im < 2; im++)
#pragma unroll
            for (int jn = 0; jn < 8; jn++)
#pragma unroll
                for (int e = 0; e < 4; e++) acc[im][jn][e] = 0.f;

        // prologue: slab 0 -> stage 0
#pragma unroll
        for (int it = 0; it < 4; it++) {
            int li = tid + it * 256;
            int code = li >> 3, u = li & 7;
            CP_ASYNC16(sb + SM_B + code * 128 + (uint32_t)((u ^ (code & 7)) * 16),
                       g_Cb + (size_t)(kt + code) * DDIM + u * 8);
        }
        CP_COMMIT();

#pragma unroll
        for (int s = 0; s < 4; s++) {
            const int st = s & 1;
            if (s < 3) {
                const int ns = s + 1, nst = ns & 1;
#pragma unroll
                for (int it = 0; it < 4; it++) {
                    int li = tid + it * 256;
                    int code = li >> 3, u = li & 7;
                    CP_ASYNC16(sb + SM_B + nst * 16384 + code * 128
                               + (uint32_t)((u ^ (code & 7)) * 16),
                               g_Cb + (size_t)(kt + code) * DDIM + ns * 64 + u * 8);
                }
                CP_COMMIT();
                CP_WAIT(1);
            } else {
                CP_WAIT(0);
            }
            __syncthreads();

#pragma unroll
            for (int ksl = 0; ksl < 4; ksl++) {
                uint32_t ah[8], bh[16];
                const int uA = s * 8 + ksl * 2 + (lane >> 4);
#pragma unroll
                for (int im = 0; im < 2; im++) {
                    int row = wm0 + im * 16 + (lane & 15);
                    uint32_t sw = (uint32_t)((uA & 24) | ((uA & 7) ^ (row & 7)));
                    ldm_x4(&ah[im * 4], sb + SM_A + row * 512 + sw * 16);
                }
                const int uB = ksl * 2 + ((lane >> 3) & 1);
#pragma unroll
                for (int j4 = 0; j4 < 4; j4++) {
                    int code = wn0 + j4 * 16 + ((lane >> 4) * 8) + (lane & 7);
                    ldm_x4(&bh[j4 * 4], sb + SM_B + st * 16384 + code * 128
                                        + (uint32_t)((uB ^ (code & 7)) * 16));
                }
#pragma unroll
                for (int im = 0; im < 2; im++)
#pragma unroll
                    for (int jn = 0; jn < 8; jn++)
                        mma16816(acc[im][jn], &ah[im * 4],
                                 &bh[(jn >> 1) * 4 + (jn & 1) * 2]);
            }
            __syncthreads();
        }

        // ---- epilogue: scores + per-thread running top-3 ----
#pragma unroll
        for (int im = 0; im < 2; im++)
#pragma unroll
            for (int jn = 0; jn < 8; jn++)
#pragma unroll
                for (int e = 0; e < 4; e++) {
                    const int rs  = im * 2 + (e >> 1);
                    const int col = kt + wn0 + jn * 8 + (lane & 3) * 2 + (e & 1);
                    float s = fmaf(-2.f, acc[im][jn][e], cn[col]);
                    if (s < tv[rs][2]) {
                        if (s < tv[rs][1]) {
                            tv[rs][2] = tv[rs][1]; ti[rs][2] = ti[rs][1];
                            if (s < tv[rs][0]) {
                                tv[rs][1] = tv[rs][0]; ti[rs][1] = ti[rs][0];
                                tv[rs][0] = s;         ti[rs][0] = col;
                            } else { tv[rs][1] = s; ti[rs][1] = col; }
                        } else { tv[rs][2] = s; ti[rs][2] = col; }
                    }
                }
    }

    // ---- CTA merge: 8 contributors x 3 -> top-6 per row ----
    __syncthreads();
    float* rv = (float*)(smem + SM_B);          // [128][8][3]
    int*   ri = (int*)(smem + SM_B + 12288);    // [128][8][3]
    const int cid = (wid & 1) * 4 + (lane & 3);
#pragma unroll
    for (int im = 0; im < 2; im++)
#pragma unroll
        for (int half = 0; half < 2; half++) {
            const int rs  = im * 2 + half;
            const int row = wm0 + im * 16 + (lane >> 2) + half * 8;
#pragma unroll
            for (int sl = 0; sl < 3; sl++) {
                rv[(row * 8 + cid) * 3 + sl] = tv[rs][sl];
                ri[(row * 8 + cid) * 3 + sl] = ti[rs][sl];
            }
        }
    __syncthreads();
    if (tid < 128) {
        float v[6]; int ix[6];
#pragma unroll
        for (int j = 0; j < 6; j++) { v[j] = 3.4e38f; ix[j] = 0x7FFFFFFF; }
        for (int c = 0; c < 24; c++) {
            float val = rv[tid * 24 + c];
            int   id  = ri[tid * 24 + c];
            if (val < v[5] || (val == v[5] && id < ix[5])) {
                v[5] = val; ix[5] = id;
#pragma unroll
                for (int j = 5; j > 0; j--) {
                    if (v[j] < v[j-1] || (v[j] == v[j-1] && ix[j] < ix[j-1])) {
                        float tv_ = v[j]; v[j] = v[j-1]; v[j-1] = tv_;
                        int   ti_ = ix[j]; ix[j] = ix[j-1]; ix[j-1] = ti_;
                    }
                }
            }
        }
        int* gc = g_cand + (size_t)(brow + tid) * 8;
        ((int4*)gc)[0] = make_int4(ix[0], ix[1], ix[2], ix[3]);
        ((int4*)gc)[1] = make_int4(ix[4], ix[5], ix[0], ix[0]);
    }
}

// ---------------------------------------------------------------------------
// Exact fp32 re-rank of 6 candidates + gather + straight-through output
// + SSE partials + histogram. One warp per row. (Top-6 is the PROVEN
// candidate count for single-bf16 score noise; top-2 measurably fails.)
// ---------------------------------------------------------------------------
__global__ __launch_bounds__(256) void vq_output_kernel(
    const float* __restrict__ X, const float* __restrict__ C,
    float* __restrict__ outQ, float* __restrict__ outIdx, int N)
{
    __shared__ double wsse[8];
    int gw   = (blockIdx.x * 256 + threadIdx.x) >> 5;
    int lane = threadIdx.x & 31;
    int wib  = threadIdx.x >> 5;

    if (gw < N) {
        const int4 c0 = ((const int4*)(g_cand + (size_t)gw * 8))[0];
        const int4 c1 = ((const int4*)(g_cand + (size_t)gw * 8))[1];
        int cand[6] = { c0.x, c0.y, c0.z, c0.w, c1.x, c1.y };

        const float4* xp = (const float4*)(X + (size_t)gw * DDIM);
        float4 x0 = xp[lane], x1 = xp[lane + 32];

        float bestS = 3.4e38f;
        int   bestI = 0x7FFFFFFF;
        float4 bq0 = x0, bq1 = x1;
#pragma unroll
        for (int j = 0; j < 6; j++) {
            const int idx = cand[j];
            const float4* cp = (const float4*)(C + (size_t)idx * DDIM);
            float4 q0 = cp[lane], q1 = cp[lane + 32];
            float d = x0.x*q0.x + x0.y*q0.y + x0.z*q0.z + x0.w*q0.w
                    + x1.x*q1.x + x1.y*q1.y + x1.z*q1.z + x1.w*q1.w;
#pragma unroll
            for (int o = 16; o > 0; o >>= 1) d += __shfl_xor_sync(0xffffffffu, d, o);
            float s = g_cnorm[idx] - 2.f * d;
            bool better = (s < bestS) || (s == bestS && idx < bestI);
            if (better) { bestS = s; bestI = idx; bq0 = q0; bq1 = q1; }
        }

        float4 o0, o1;
        double sse = 0.0;
        float dx;
        dx = bq0.x - x0.x; o0.x = x0.x + dx; sse += (double)dx * dx;
        dx = bq0.y - x0.y; o0.y = x0.y + dx; sse += (double)dx * dx;
        dx = bq0.z - x0.z; o0.z = x0.z + dx; sse += (double)dx * dx;
        dx = bq0.w - x0.w; o0.w = x0.w + dx; sse += (double)dx * dx;
        dx = bq1.x - x1.x; o1.x = x1.x + dx; sse += (double)dx * dx;
        dx = bq1.y - x1.y; o1.y = x1.y + dx; sse += (double)dx * dx;
        dx = bq1.z - x1.z; o1.z = x1.z + dx; sse += (double)dx * dx;
        dx = bq1.w - x1.w; o1.w = x1.w + dx; sse += (double)dx * dx;

        float4* op = (float4*)(outQ + (size_t)gw * DDIM);
        op[lane] = o0;
        op[lane + 32] = o1;

#pragma unroll
        for (int o = 16; o > 0; o >>= 1) sse += __shfl_down_sync(0xffffffffu, sse, o);
        if (lane == 0) {
            wsse[wib] = sse;
            atomicAdd(&g_hist[bestI], 1);
            outIdx[gw] = (float)bestI;
        }
    } else if (lane == 0) {
        wsse[wib] = 0.0;
    }
    __syncthreads();
    if (threadIdx.x == 0) {
        double s = 0.0;
#pragma unroll
        for (int i = 0; i < 8; i++) s += wsse[i];
        g_ssep[blockIdx.x] = s;
    }
}

// ---------------------------------------------------------------------------
__global__ void vq_finalize_kernel(float* __restrict__ outS, int N, int K)
{
    __shared__ double red[256];
    int t = threadIdx.x;
    double s = 0.0;
    for (int i = t; i < NPART; i += 256) s += g_ssep[i];
    red[t] = s;
    __syncthreads();
    for (int st = 128; st > 0; st >>= 1) { if (t < st) red[t] += red[t + st]; __syncthreads(); }
    double sseTot = red[0];
    __syncthreads();

    double h = 0.0;
    for (int k = t; k < K; k += 256) {
        float pr = (float)g_hist[k] / (float)N;
        h += (double)(pr * logf(pr + 1e-10f));
    }
    red[t] = h;
    __syncthreads();
    for (int st = 128; st > 0; st >>= 1) { if (t < st) red[t] += red[t + st]; __syncthreads(); }
    if (t == 0) {
        double mean = sseTot / ((double)N * (double)DDIM);
        outS[0] = (float)(1.25 * mean);
        outS[1] = (float)exp(-red[0]);
    }
}

// ---------------------------------------------------------------------------
extern "C" void kernel_launch(void* const* d_in, const int* in_sizes, int n_in,
                              void* d_out, int out_size)
{
    const float* X = (const float*)d_in[0];   // [N, 256]
    const float* C = (const float*)d_in[1];   // [K, 256]
    const int N = in_sizes[0] / DDIM;         // 131072
    const int K = in_sizes[1] / DDIM;         // 1024

    float* out        = (float*)d_out;
    float* outQ       = out;                      // N*D quantized_st
    float* outIdx     = out + (size_t)N * DDIM;   // N indices (as f32)
    float* outScalars = outIdx + N;               // loss, perplexity

    static bool attr_set = false;
    if (!attr_set) {
        cudaFuncSetAttribute(vq_gemm_kernel,
                             cudaFuncAttributeMaxDynamicSharedMemorySize, SMEM_BYTES);
        attr_set = true;
    }

    const int n8C = K * DDIM / 8;             // 32768
    const int n8X = N * DDIM / 8;             // 4194304

    vq_zero_kernel<<<(K + 255) / 256, 256>>>(K);                              // 1
    vq_cnorm_kernel<<<(K * 32 + 255) / 256, 256>>>(C, K);                     // 2
    vq_convert_kernel<<<(n8C + 255) / 256, 256>>>(C, 1, n8C);                 // 3
    vq_convert_kernel<<<(n8X + 255) / 256, 256>>>(X, 0, n8X);                 // 4
    vq_gemm_kernel<<<N / 128, 256, SMEM_BYTES>>>();                           // 5
    vq_output_kernel<<<N / 8, 256>>>(X, C, outQ, outIdx, N);                  // 6
    vq_finalize_kernel<<<1, 256>>>(outScalars, N, K);                         // 7
}

// round 17
// speedup vs baseline: 1.5848x; 1.0120x over previous
#include <cuda_runtime.h>
#include <cuda_bf16.h>
#include <math.h>
#include <stdint.h>

#define DDIM 256
#define MAXN 131072
#define MAXK 1024
#define NPART 16384   // MAXN / 8 rows-per-output-block

// ---------------- device scratch (no allocations allowed) ----------------
__device__ __nv_bfloat16 g_Xb[MAXN * DDIM];
__device__ __nv_bfloat16 g_Cb[MAXK * DDIM];
__device__ float  g_cnorm[MAXK];
__device__ int    g_cand[MAXN * 8];     // 6 candidate indices + 2 pad per row
__device__ float  g_candv[MAXN * 8];    // 6 sorted noisy scores + 2 pad per row
__device__ int    g_hist[MAXK];
__device__ double g_ssep[NPART];

// ---------------- PTX helpers (plain sm_80-class PTX only) ----------------
__device__ __forceinline__ uint32_t smem_u32(const void* p) {
    uint32_t a;
    asm("{ .reg .u64 t; cvta.to.shared.u64 t, %1; cvt.u32.u64 %0, t; }" : "=r"(a) : "l"(p));
    return a;
}
#define CP_ASYNC16(dst, src) \
    asm volatile("cp.async.cg.shared.global [%0], [%1], 16;" :: "r"(dst), "l"(src))
#define CP_COMMIT()  asm volatile("cp.async.commit_group;" ::: "memory")
#define CP_WAIT(n)   asm volatile("cp.async.wait_group %0;" :: "n"(n) : "memory")

__device__ __forceinline__ void ldm_x4(uint32_t* r, uint32_t addr) {
    asm volatile("ldmatrix.sync.aligned.m8n8.x4.shared.b16 {%0,%1,%2,%3}, [%4];"
                 : "=r"(r[0]), "=r"(r[1]), "=r"(r[2]), "=r"(r[3]) : "r"(addr));
}
__device__ __forceinline__ void mma16816(float* c, const uint32_t* a, const uint32_t* b) {
    asm volatile(
        "mma.sync.aligned.m16n8k16.row.col.f32.bf16.bf16.f32 "
        "{%0,%1,%2,%3}, {%4,%5,%6,%7}, {%8,%9}, {%0,%1,%2,%3};"
        : "+f"(c[0]), "+f"(c[1]), "+f"(c[2]), "+f"(c[3])
        : "r"(a[0]), "r"(a[1]), "r"(a[2]), "r"(a[3]), "r"(b[0]), "r"(b[1]));
}

// ---------------------------------------------------------------------------
__global__ void vq_zero_kernel(int K)
{
    int t = blockIdx.x * blockDim.x + threadIdx.x;
    if (t < K) g_hist[t] = 0;
}

// ---------------------------------------------------------------------------
__global__ void vq_cnorm_kernel(const float* __restrict__ C, int K)
{
    int warp = (blockIdx.x * blockDim.x + threadIdx.x) >> 5;
    int lane = threadIdx.x & 31;
    if (warp >= K) return;
    const float4* cp = (const float4*)(C + (size_t)warp * DDIM);
    float s = 0.f;
#pragma unroll
    for (int i = 0; i < 2; i++) {
        float4 v = cp[lane + i * 32];
        s += v.x * v.x + v.y * v.y + v.z * v.z + v.w * v.w;
    }
#pragma unroll
    for (int o = 16; o > 0; o >>= 1) s += __shfl_down_sync(0xffffffffu, s, o);
    if (lane == 0) g_cnorm[warp] = s;
}

// ---------------------------------------------------------------------------
// fp32 -> bf16 (rn), 8 elems / thread, 16B stores. Destination global
// selected in DEVICE code via mode flag (host-side __device__ symbol
// addresses are invalid — the R8/R9/R11 bug).
// ---------------------------------------------------------------------------
__global__ void vq_convert_kernel(const float* __restrict__ src, int mode, int n8)
{
    int t = blockIdx.x * blockDim.x + threadIdx.x;
    if (t >= n8) return;
    const float4* s4 = (const float4*)src;
    float4 a = s4[t * 2], b = s4[t * 2 + 1];
    uint4 r;
    r.x = (uint32_t)__bfloat16_as_ushort(__float2bfloat16(a.x))
        | ((uint32_t)__bfloat16_as_ushort(__float2bfloat16(a.y)) << 16);
    r.y = (uint32_t)__bfloat16_as_ushort(__float2bfloat16(a.z))
        | ((uint32_t)__bfloat16_as_ushort(__float2bfloat16(a.w)) << 16);
    r.z = (uint32_t)__bfloat16_as_ushort(__float2bfloat16(b.x))
        | ((uint32_t)__bfloat16_as_ushort(__float2bfloat16(b.y)) << 16);
    r.w = (uint32_t)__bfloat16_as_ushort(__float2bfloat16(b.z))
        | ((uint32_t)__bfloat16_as_ushort(__float2bfloat16(b.w)) << 16);
    uint4* dst = (uint4*)(mode ? g_Cb : g_Xb);
    dst[t] = r;
}

// ---------------------------------------------------------------------------
// bf16 HMMA distance GEMM + per-row top-6 candidates (sorted, with values).
// EXACT R7/R15 pipeline (proven green); merge tail additionally stores the
// 6 sorted noisy scores for the output kernel's threshold dispatch.
// ---------------------------------------------------------------------------
#define SM_CN 0            // 4 KB cnorm
#define SM_A  4096         // 64 KB: A bf16 (row 512B, swizzled)
#define SM_B  69632        // 2 stages x 16 KB
#define SMEM_BYTES 102400

__global__ __launch_bounds__(256, 2) void vq_gemm_kernel()
{
    extern __shared__ char smem[];
    const uint32_t sb = smem_u32(smem);
    const int tid  = threadIdx.x;
    const int lane = tid & 31;
    const int wid  = tid >> 5;
    const int wm0  = (wid >> 1) * 32;     // warp M origin (4)
    const int wn0  = (wid & 1) * 64;      // warp N origin (2)
    const int brow = blockIdx.x * 128;

    // ---- cnorm (4 KB) + resident A (64 KB) via cp.async ----
    CP_ASYNC16(sb + SM_CN + tid * 16, g_cnorm + tid * 4);
#pragma unroll
    for (int it = 0; it < 16; it++) {
        int li  = tid + it * 256;           // 0..4095
        int row = li >> 5, u = li & 31;
        uint32_t sw = (uint32_t)((u & 24) | ((u & 7) ^ (row & 7)));
        CP_ASYNC16(sb + SM_A + row * 512 + sw * 16,
                   g_Xb + (size_t)(brow + row) * DDIM + u * 8);
    }
    CP_COMMIT();

    // per-thread top-3 for 4 row-slots
    float tv[4][3];
    int   ti[4][3];
#pragma unroll
    for (int i = 0; i < 4; i++)
#pragma unroll
        for (int j = 0; j < 3; j++) { tv[i][j] = 3.4e38f; ti[i][j] = 0x7FFFFFFF; }

    CP_WAIT(0);
    __syncthreads();

    const float* cn = (const float*)smem;

    for (int p = 0; p < 8; p++) {
        const int kt = p * 128;

        float acc[2][8][4];
#pragma unroll
        for (int im = 0; im < 2; im++)
#pragma unroll
            for (int jn = 0; jn < 8; jn++)
#pragma unroll
                for (int e = 0; e < 4; e++) acc[im][jn][e] = 0.f;

        // prologue: slab 0 -> stage 0
#pragma unroll
        for (int it = 0; it < 4; it++) {
            int li = tid + it * 256;
            int code = li >> 3, u = li & 7;
            CP_ASYNC16(sb + SM_B + code * 128 + (uint32_t)((u ^ (code & 7)) * 16),
                       g_Cb + (size_t)(kt + code) * DDIM + u * 8);
        }
        CP_COMMIT();

#pragma unroll
        for (int s = 0; s < 4; s++) {
            const int st = s & 1;
            if (s < 3) {
                const int ns = s + 1, nst = ns & 1;
#pragma unroll
                for (int it = 0; it < 4; it++) {
                    int li = tid + it * 256;
                    int code = li >> 3, u = li & 7;
                    CP_ASYNC16(sb + SM_B + nst * 16384 + code * 128
                               + (uint32_t)((u ^ (code & 7)) * 16),
                               g_Cb + (size_t)(kt + code) * DDIM + ns * 64 + u * 8);
                }
                CP_COMMIT();
                CP_WAIT(1);
            } else {
                CP_WAIT(0);
            }
            __syncthreads();

#pragma unroll
            for (int ksl = 0; ksl < 4; ksl++) {
                uint32_t ah[8], bh[16];
                const int uA = s * 8 + ksl * 2 + (lane >> 4);
#pragma unroll
                for (int im = 0; im < 2; im++) {
                    int row = wm0 + im * 16 + (lane & 15);
                    uint32_t sw = (uint32_t)((uA & 24) | ((uA & 7) ^ (row & 7)));
                    ldm_x4(&ah[im * 4], sb + SM_A + row * 512 + sw * 16);
                }
                const int uB = ksl * 2 + ((lane >> 3) & 1);
#pragma unroll
                for (int j4 = 0; j4 < 4; j4++) {
                    int code = wn0 + j4 * 16 + ((lane >> 4) * 8) + (lane & 7);
                    ldm_x4(&bh[j4 * 4], sb + SM_B + st * 16384 + code * 128
                                        + (uint32_t)((uB ^ (code & 7)) * 16));
                }
#pragma unroll
                for (int im = 0; im < 2; im++)
#pragma unroll
                    for (int jn = 0; jn < 8; jn++)
                        mma16816(acc[im][jn], &ah[im * 4],
                                 &bh[(jn >> 1) * 4 + (jn & 1) * 2]);
            }
            __syncthreads();
        }

        // ---- epilogue: scores + per-thread running top-3 ----
#pragma unroll
        for (int im = 0; im < 2; im++)
#pragma unroll
            for (int jn = 0; jn < 8; jn++)
#pragma unroll
                for (int e = 0; e < 4; e++) {
                    const int rs  = im * 2 + (e >> 1);
                    const int col = kt + wn0 + jn * 8 + (lane & 3) * 2 + (e & 1);
                    float s = fmaf(-2.f, acc[im][jn][e], cn[col]);
                    if (s < tv[rs][2]) {
                        if (s < tv[rs][1]) {
                            tv[rs][2] = tv[rs][1]; ti[rs][2] = ti[rs][1];
                            if (s < tv[rs][0]) {
                                tv[rs][1] = tv[rs][0]; ti[rs][1] = ti[rs][0];
                                tv[rs][0] = s;         ti[rs][0] = col;
                            } else { tv[rs][1] = s; ti[rs][1] = col; }
                        } else { tv[rs][2] = s; ti[rs][2] = col; }
                    }
                }
    }

    // ---- CTA merge: 8 contributors x 3 -> top-6 per row (values + idx) ----
    __syncthreads();
    float* rv = (float*)(smem + SM_B);          // [128][8][3]
    int*   ri = (int*)(smem + SM_B + 12288);    // [128][8][3]
    const int cid = (wid & 1) * 4 + (lane & 3);
#pragma unroll
    for (int im = 0; im < 2; im++)
#pragma unroll
        for (int half = 0; half < 2; half++) {
            const int rs  = im * 2 + half;
            const int row = wm0 + im * 16 + (lane >> 2) + half * 8;
#pragma unroll
            for (int sl = 0; sl < 3; sl++) {
                rv[(row * 8 + cid) * 3 + sl] = tv[rs][sl];
                ri[(row * 8 + cid) * 3 + sl] = ti[rs][sl];
            }
        }
    __syncthreads();
    if (tid < 128) {
        float v[6]; int ix[6];
#pragma unroll
        for (int j = 0; j < 6; j++) { v[j] = 3.4e38f; ix[j] = 0x7FFFFFFF; }
        for (int c = 0; c < 24; c++) {
            float val = rv[tid * 24 + c];
            int   id  = ri[tid * 24 + c];
            if (val < v[5] || (val == v[5] && id < ix[5])) {
                v[5] = val; ix[5] = id;
#pragma unroll
                for (int j = 5; j > 0; j--) {
                    if (v[j] < v[j-1] || (v[j] == v[j-1] && ix[j] < ix[j-1])) {
                        float tv_ = v[j]; v[j] = v[j-1]; v[j-1] = tv_;
                        int   ti_ = ix[j]; ix[j] = ix[j-1]; ix[j-1] = ti_;
                    }
                }
            }
        }
        int* gc = g_cand + (size_t)(brow + tid) * 8;
        ((int4*)gc)[0] = make_int4(ix[0], ix[1], ix[2], ix[3]);
        ((int4*)gc)[1] = make_int4(ix[4], ix[5], ix[0], ix[0]);
        float* gv = g_candv + (size_t)(brow + tid) * 8;
        ((float4*)gv)[0] = make_float4(v[0], v[1], v[2], v[3]);
        ((float4*)gv)[1] = make_float4(v[4], v[5], v[0], v[0]);
    }
}

// ---------------------------------------------------------------------------
// Output kernel with threshold dispatch: the top-6 noisy scores are sorted;
// any candidate with v[j] >= v[0] + THR cannot be the exact argmin
// (THR = 1.0 ~ 14 sigma of a score-error difference). ~97% of rows have
// only 1 viable candidate -> gather it directly, no re-rank. Otherwise
// exact fp32 re-rank of the viable prefix. Warp-uniform, deterministic.
// ---------------------------------------------------------------------------
#define RERANK_THR 1.0f

__global__ __launch_bounds__(256) void vq_output_kernel(
    const float* __restrict__ X, const float* __restrict__ C,
    float* __restrict__ outQ, float* __restrict__ outIdx, int N)
{
    __shared__ double wsse[8];
    int gw   = (blockIdx.x * 256 + threadIdx.x) >> 5;
    int lane = threadIdx.x & 31;
    int wib  = threadIdx.x >> 5;

    if (gw < N) {
        const int4 c0 = ((const int4*)(g_cand + (size_t)gw * 8))[0];
        const int4 c1 = ((const int4*)(g_cand + (size_t)gw * 8))[1];
        int cand[6] = { c0.x, c0.y, c0.z, c0.w, c1.x, c1.y };
        const float4 vA = ((const float4*)(g_candv + (size_t)gw * 8))[0];
        const float4 vB = ((const float4*)(g_candv + (size_t)gw * 8))[1];
        float vv[6] = { vA.x, vA.y, vA.z, vA.w, vB.x, vB.y };

        int m = 1;                      // viable-prefix length (values sorted)
#pragma unroll
        for (int j = 1; j < 6; j++) m += (vv[j] < vv[0] + RERANK_THR) ? 1 : 0;

        const float4* xp = (const float4*)(X + (size_t)gw * DDIM);
        float4 x0 = xp[lane], x1 = xp[lane + 32];

        int bestI;
        float4 bq0, bq1;
        if (m == 1) {                   // fast path: winner certain
            bestI = cand[0];
            const float4* cp = (const float4*)(C + (size_t)bestI * DDIM);
            bq0 = cp[lane]; bq1 = cp[lane + 32];
        } else {                        // slow path: exact re-rank of prefix
            float bestS = 3.4e38f;
            bestI = 0x7FFFFFFF;
            bq0 = x0; bq1 = x1;
            for (int j = 0; j < m; j++) {
                const int idx = cand[j];
                const float4* cp = (const float4*)(C + (size_t)idx * DDIM);
                float4 q0 = cp[lane], q1 = cp[lane + 32];
                float d = x0.x*q0.x + x0.y*q0.y + x0.z*q0.z + x0.w*q0.w
                        + x1.x*q1.x + x1.y*q1.y + x1.z*q1.z + x1.w*q1.w;
#pragma unroll
                for (int o = 16; o > 0; o >>= 1) d += __shfl_xor_sync(0xffffffffu, d, o);
                float s = g_cnorm[idx] - 2.f * d;
                bool better = (s < bestS) || (s == bestS && idx < bestI);
                if (better) { bestS = s; bestI = idx; bq0 = q0; bq1 = q1; }
            }
        }

        float4 o0, o1;
        double sse = 0.0;
        float dx;
        dx = bq0.x - x0.x; o0.x = x0.x + dx; sse += (double)dx * dx;
        dx = bq0.y - x0.y; o0.y = x0.y + dx; sse += (double)dx * dx;
        dx = bq0.z - x0.z; o0.z = x0.z + dx; sse += (double)dx * dx;
        dx = bq0.w - x0.w; o0.w = x0.w + dx; sse += (double)dx * dx;
        dx = bq1.x - x1.x; o1.x = x1.x + dx; sse += (double)dx * dx;
        dx = bq1.y - x1.y; o1.y = x1.y + dx; sse += (double)dx * dx;
        dx = bq1.z - x1.z; o1.z = x1.z + dx; sse += (double)dx * dx;
        dx = bq1.w - x1.w; o1.w = x1.w + dx; sse += (double)dx * dx;

        float4* op = (float4*)(outQ + (size_t)gw * DDIM);
        op[lane] = o0;
        op[lane + 32] = o1;

#pragma unroll
        for (int o = 16; o > 0; o >>= 1) sse += __shfl_down_sync(0xffffffffu, sse, o);
        if (lane == 0) {
            wsse[wib] = sse;
            atomicAdd(&g_hist[bestI], 1);
            outIdx[gw] = (float)bestI;
        }
    } else if (lane == 0) {
        wsse[wib] = 0.0;
    }
    __syncthreads();
    if (threadIdx.x == 0) {
        double s = 0.0;
#pragma unroll
        for (int i = 0; i < 8; i++) s += wsse[i];
        g_ssep[blockIdx.x] = s;
    }
}

// ---------------------------------------------------------------------------
__global__ void vq_finalize_kernel(float* __restrict__ outS, int N, int K)
{
    __shared__ double red[256];
    int t = threadIdx.x;
    double s = 0.0;
    for (int i = t; i < NPART; i += 256) s += g_ssep[i];
    red[t] = s;
    __syncthreads();
    for (int st = 128; st > 0; st >>= 1) { if (t < st) red[t] += red[t + st]; __syncthreads(); }
    double sseTot = red[0];
    __syncthreads();

    double h = 0.0;
    for (int k = t; k < K; k += 256) {
        float pr = (float)g_hist[k] / (float)N;
        h += (double)(pr * logf(pr + 1e-10f));
    }
    red[t] = h;
    __syncthreads();
    for (int st = 128; st > 0; st >>= 1) { if (t < st) red[t] += red[t + st]; __syncthreads(); }
    if (t == 0) {
        double mean = sseTot / ((double)N * (double)DDIM);
        outS[0] = (float)(1.25 * mean);
        outS[1] = (float)exp(-red[0]);
    }
}

// ---------------------------------------------------------------------------
extern "C" void kernel_launch(void* const* d_in, const int* in_sizes, int n_in,
                              void* d_out, int out_size)
{
    const float* X = (const float*)d_in[0];   // [N, 256]
    const float* C = (const float*)d_in[1];   // [K, 256]
    const int N = in_sizes[0] / DDIM;         // 131072
    const int K = in_sizes[1] / DDIM;         // 1024

    float* out        = (float*)d_out;
    float* outQ       = out;                      // N*D quantized_st
    float* outIdx     = out + (size_t)N * DDIM;   // N indices (as f32)
    float* outScalars = outIdx + N;               // loss, perplexity

    static bool attr_set = false;
    if (!attr_set) {
        cudaFuncSetAttribute(vq_gemm_kernel,
                             cudaFuncAttributeMaxDynamicSharedMemorySize, SMEM_BYTES);
        attr_set = true;
    }

    const int n8C = K * DDIM / 8;             // 32768
    const int n8X = N * DDIM / 8;             // 4194304

    vq_zero_kernel<<<(K + 255) / 256, 256>>>(K);                              // 1
    vq_cnorm_kernel<<<(K * 32 + 255) / 256, 256>>>(C, K);                     // 2
    vq_convert_kernel<<<(n8C + 255) / 256, 256>>>(C, 1, n8C);                 // 3
    vq_convert_kernel<<<(n8X + 255) / 256, 256>>>(X, 0, n8X);                 // 4
    vq_gemm_kernel<<<N / 128, 256, SMEM_BYTES>>>();                           // 5
    vq_output_kernel<<<N / 8, 256>>>(X, C, outQ, outIdx, N);                  // 6
    vq_finalize_kernel<<<1, 256>>>(outScalars, N, K);                         // 7
}